// round 5
// baseline (speedup 1.0000x reference)
#include <cuda_runtime.h>
#include <math.h>

#define NQ 14
#define NSTATE (1 << NQ)
#define NT 1024
#define PI_F 3.14159265358979323846f

typedef unsigned long long u64;

// ---------------------------------------------------------------------------
__device__ __forceinline__ u64 pk(float a, float b) {
    u64 r; asm("mov.b64 %0,{%1,%2};" : "=l"(r) : "f"(a), "f"(b)); return r;
}
__device__ __forceinline__ void unpk(u64 v, float& a, float& b) {
    asm("mov.b64 {%0,%1},%2;" : "=f"(a), "=f"(b) : "l"(v));
}
__device__ __forceinline__ u64 fma2(u64 a, u64 b, u64 c) {
    u64 d; asm("fma.rn.f32x2 %0,%1,%2,%3;" : "=l"(d) : "l"(a), "l"(b), "l"(c)); return d;
}
__device__ __forceinline__ u64 mul2(u64 a, u64 b) {
    u64 d; asm("mul.rn.f32x2 %0,%1,%2;" : "=l"(d) : "l"(a), "l"(b)); return d;
}
__device__ __forceinline__ u64 add2(u64 a, u64 b) {
    u64 d; asm("add.rn.f32x2 %0,%1,%2;" : "=l"(d) : "l"(a), "l"(b)); return d;
}

__device__ __forceinline__ float2 cmul(float2 a, float2 b) {
    float2 r;
    r.x = a.x * b.x - a.y * b.y;
    r.y = a.x * b.y + a.y * b.x;
    return r;
}

// swizzle: slot bits1-4 = a1-4 ^ a5-8 ^ a9-12; bit0 = a0 (keeps u64 pairing)
__host__ __device__ constexpr int slotf(int a) {
    return a ^ (((a >> 5) & 15) << 1) ^ (((a >> 9) & 15) << 1);
}

// shared tables
__shared__ float2 gT[3][NQ][12];  // splat coeffs; [13] = 6-entry reg-gate layout
__shared__ float2 v0[NQ][2];      // per-qubit vector after encoding + layer0
__shared__ float  red[32][16];

__device__ __forceinline__ u64 ld8(const float2* p) {
    return *reinterpret_cast<const u64*>(p);
}

// U = RZ(rz) @ RY(ry) @ RX(rx)
__device__ __forceinline__ void make_u(float rx, float ry, float rz, float2 U[4]) {
    float cx, sx, cy, sy, cz, sz;
    sincosf(0.5f * rx, &sx, &cx);
    sincosf(0.5f * ry, &sy, &cy);
    sincosf(0.5f * rz, &sz, &cz);
    float2 M00 = { cy * cx,  sy * sx };
    float2 M01 = {-sy * cx, -cy * sx };
    float2 M10 = { sy * cx, -cy * sx };
    float2 M11 = { cy * cx, -sy * sx };
    float2 p = { cz, -sz };
    float2 q = { cz,  sz };
    U[0] = cmul(p, M00);
    U[1] = cmul(p, M01);
    U[2] = cmul(q, M10);
    U[3] = cmul(q, M11);
}

__device__ __forceinline__ void bfly(u64& a0r, u64& a0i, u64& a1r, u64& a1i,
                                     u64 X00, u64 Y00, u64 M00,
                                     u64 X01, u64 Y01, u64 M01,
                                     u64 X10, u64 Y10, u64 M10,
                                     u64 X11, u64 Y11, u64 M11) {
    u64 n0r = fma2(M01, a1i, fma2(X01, a1r, fma2(M00, a0i, mul2(X00, a0r))));
    u64 n0i = fma2(X01, a1i, fma2(Y01, a1r, fma2(X00, a0i, mul2(Y00, a0r))));
    u64 n1r = fma2(M11, a1i, fma2(X11, a1r, fma2(M10, a0i, mul2(X10, a0r))));
    u64 n1i = fma2(X11, a1i, fma2(Y11, a1r, fma2(X10, a0i, mul2(Y10, a0r))));
    a0r = n0r; a0i = n0i; a1r = n1r; a1i = n1i;
}

// 3 gates on jj bits 0,1,2 (qubits QA,QB,QC), 8 packed pairs in registers
template<int QA, int QB, int QC>
__device__ __forceinline__ void gates3(u64* cr, u64* ci, const float2 (*g)[12]) {
#pragma unroll
    for (int k = 0; k < 3; k++) {
        const int q = (k == 0) ? QA : (k == 1) ? QB : QC;
        const u64 X00 = ld8(&g[q][0]),  Y00 = ld8(&g[q][1]),  M00 = ld8(&g[q][2]);
        const u64 X01 = ld8(&g[q][3]),  Y01 = ld8(&g[q][4]),  M01 = ld8(&g[q][5]);
        const u64 X10 = ld8(&g[q][6]),  Y10 = ld8(&g[q][7]),  M10 = ld8(&g[q][8]);
        const u64 X11 = ld8(&g[q][9]),  Y11 = ld8(&g[q][10]), M11 = ld8(&g[q][11]);
#pragma unroll
        for (int jj = 0; jj < 8; jj++) {
            if (jj & (1 << k)) continue;
            const int j2 = jj | (1 << k);
            bfly(cr[jj], ci[jj], cr[j2], ci[j2],
                 X00, Y00, M00, X01, Y01, M01, X10, Y10, M10, X11, Y11, M11);
        }
    }
}

// in-register gate on pack bit (qubit 13); g[13] 6-entry layout
__device__ __forceinline__ void reggate13(u64* cr, u64* ci, const float2 (*g)[12]) {
    const u64 A  = ld8(&g[13][0]), B  = ld8(&g[13][1]);
    const u64 E  = ld8(&g[13][2]), F  = ld8(&g[13][3]);
    const u64 Cm = ld8(&g[13][4]), Dm = ld8(&g[13][5]);
#pragma unroll
    for (int jj = 0; jj < 8; jj++) {
        float r0, r1, i0, i1;
        unpk(cr[jj], r0, r1);
        unpk(ci[jj], i0, i1);
        const u64 sar = pk(r1, r0), sai = pk(i1, i0);
        const u64 nr = fma2(Dm, sai, fma2(Cm, ci[jj], fma2(B, sar, mul2(A, cr[jj]))));
        const u64 ni = fma2(B,  sai, fma2(A,  ci[jj], fma2(F, sar, mul2(E, cr[jj]))));
        cr[jj] = nr; ci[jj] = ni;
    }
}

// shuffle gate: partner across lanes via xor mask; v = thread's bit value
__device__ __forceinline__ void shflg(u64* cr, u64* ci, const float2* gq,
                                      int mask, int v) {
    const u64 Gr = v ? ld8(&gq[9])  : ld8(&gq[0]);
    const u64 Gi = v ? ld8(&gq[10]) : ld8(&gq[1]);
    const u64 Gm = v ? ld8(&gq[11]) : ld8(&gq[2]);
    const u64 Hr = v ? ld8(&gq[6])  : ld8(&gq[3]);
    const u64 Hi = v ? ld8(&gq[7])  : ld8(&gq[4]);
    const u64 Hm = v ? ld8(&gq[8])  : ld8(&gq[5]);
#pragma unroll
    for (int jj = 0; jj < 8; jj++) {
        const u64 pr = __shfl_xor_sync(0xFFFFFFFFu, cr[jj], mask);
        const u64 pi = __shfl_xor_sync(0xFFFFFFFFu, ci[jj], mask);
        const u64 nr = fma2(Hm, pi, fma2(Hr, pr, fma2(Gm, ci[jj], mul2(Gr, cr[jj]))));
        const u64 ni = fma2(Hr, pi, fma2(Hi, pr, fma2(Gr, ci[jj], mul2(Gi, cr[jj]))));
        cr[jj] = nr; ci[jj] = ni;
    }
}

// ---------------------------------------------------------------------------
__global__ void __launch_bounds__(NT, 1)
qc_kernel(const float* __restrict__ x,
          const float* __restrict__ prx,
          const float* __restrict__ pry,
          const float* __restrict__ prz,
          const float* __restrict__ pent,
          float* __restrict__ out) {
    extern __shared__ float smem[];
    float* sre = smem;            // 16384 floats
    float* sim = smem + NSTATE;   // 16384 floats

    const int b    = blockIdx.x;
    const int tid  = threadIdx.x;
    const int lane = tid & 31;
    const int warp = tid >> 5;

    // ---- setup: coefficient tables, layers 1..3 (ent phases merged) --------
    if (tid < 42) {
        const int t = tid / NQ;
        const int i = tid % NQ;
        const int l = t + 1;
        float2 U[4];
        make_u(prx[l * NQ + i], pry[l * NQ + i], prz[l * NQ + i], U);
        if (i > 0) {
            float ce, se;
            sincosf(0.5f * pent[t * (NQ - 1) + (i - 1)], &se, &ce);
            float2 pe = { ce, -se };
            float2 qe = { ce,  se };
            U[0] = cmul(U[0], pe);
            U[2] = cmul(U[2], pe);
            U[1] = cmul(U[1], qe);
            U[3] = cmul(U[3], qe);
        }
        if (i == 13) {
            gT[t][i][0] = make_float2( U[0].x,  U[3].x);
            gT[t][i][1] = make_float2( U[1].x,  U[2].x);
            gT[t][i][2] = make_float2( U[0].y,  U[3].y);
            gT[t][i][3] = make_float2( U[1].y,  U[2].y);
            gT[t][i][4] = make_float2(-U[0].y, -U[3].y);
            gT[t][i][5] = make_float2(-U[1].y, -U[2].y);
        } else {
#pragma unroll
            for (int r = 0; r < 4; r++) {
                gT[t][i][r * 3 + 0] = make_float2( U[r].x,  U[r].x);
                gT[t][i][r * 3 + 1] = make_float2( U[r].y,  U[r].y);
                gT[t][i][r * 3 + 2] = make_float2(-U[r].y, -U[r].y);
            }
        }
    }
    if (tid >= 64 && tid < 64 + NQ) {
        const int i = tid - 64;
        float2 U[4];
        make_u(prx[i], pry[i], prz[i], U);
        const float enc = tanhf(x[b * NQ + i]) * PI_F;
        float ce, se;
        sincosf(0.5f * enc, &se, &ce);
        float2 a, c2;
        a.x  = U[0].x * ce + U[1].x * se;
        a.y  = U[0].y * ce + U[1].y * se;
        c2.x = U[2].x * ce + U[3].x * se;
        c2.y = U[2].y * ce + U[3].y * se;
        v0[i][0] = a;
        v0[i][1] = c2;
    }
    __syncthreads();

    const int l0 = lane & 1, l1 = (lane >> 1) & 1, l2 = (lane >> 2) & 1;
    const int l3 = (lane >> 3) & 1, l4 = (lane >> 4) & 1;

    // tile index bases (bit0 = pack):
    // A: lane->bits1-5, jj->bits6-8, warp->bits9-13
    // B: lane->bits4-8, jj->bits1-3, warp->bits9-13  (A<->B warp-local)
    // C: l0-2->bits1-3, warp->bits4-8, jj->bits9-11, l3->12, l4->13
    const int zA = (lane << 1) | (warp << 9);
    const int zB = (lane << 4) | (warp << 9);
    const int zC = (l0 << 1) | (l1 << 2) | (l2 << 3) | (warp << 4) |
                   (l3 << 12) | (l4 << 13);

    u64 cr[8], ci[8];

#pragma unroll 1
    for (int t = 0; t < 3; t++) {
        const float2 (*g)[12] = gT[t];

        // ================= tile A =================
        if (t == 0) {
            // init: product state with layer-0 entangle perm folded:
            // amp[z] = prod_p v0[13-p][ (z ^ (z>>1))_p ]
            const int w0 = warp & 1, w1 = (warp >> 1) & 1, w2 = (warp >> 2) & 1;
            const int w3 = (warp >> 3) & 1, w4 = (warp >> 4) & 1;
            float2 G = cmul(v0[12][l0 ^ l1], v0[11][l1 ^ l2]);
            G = cmul(G, v0[10][l2 ^ l3]);
            G = cmul(G, v0[ 9][l3 ^ l4]);
            G = cmul(G, v0[ 4][w0 ^ w1]);
            G = cmul(G, v0[ 3][w1 ^ w2]);
            G = cmul(G, v0[ 2][w2 ^ w3]);
            G = cmul(G, v0[ 1][w3 ^ w4]);
            G = cmul(G, v0[ 0][w4]);
            const float2 e0 = v0[13][l0], e1 = v0[13][l0 ^ 1];
#pragma unroll
            for (int jj = 0; jj < 8; jj++) {
                const int j0 = jj & 1, j1 = (jj >> 1) & 1, j2 = (jj >> 2) & 1;
                float2 H = cmul(G, v0[8][l4 ^ j0]);
                H = cmul(H, v0[7][j0 ^ j1]);
                H = cmul(H, v0[6][j1 ^ j2]);
                H = cmul(H, v0[5][j2 ^ w0]);
                const float2 lo = cmul(H, e0);
                const float2 hi = cmul(H, e1);
                cr[jj] = pk(lo.x, hi.x);
                ci[jj] = pk(lo.y, hi.y);
            }
        } else {
            // gray load: new[z] = stored[z ^ (z>>1)] (previous layer's entangle)
            const int ab = zA ^ (zA >> 1);
            const int sg = slotf(ab) & ~1;
#pragma unroll
            for (int jj = 0; jj < 8; jj++) {
                const int off = slotf((jj << 6) ^ (jj << 5));  // constexpr
                const int a = sg ^ off;
                u64 vr = *reinterpret_cast<const u64*>(&sre[a]);
                u64 vi = *reinterpret_cast<const u64*>(&sim[a]);
                if (l0) {
                    vr = (vr << 32) | (vr >> 32);
                    vi = (vi << 32) | (vi >> 32);
                }
                cr[jj] = vr; ci[jj] = vi;
            }
        }
        reggate13(cr, ci, g);          // q13
        gates3<7, 6, 5>(cr, ci, g);    // q7,q6,q5 (bits 6,7,8)
        shflg(cr, ci, g[9], 8,  l3);   // q9 (bit4)
        shflg(cr, ci, g[8], 16, l4);   // q8 (bit5)
        {
            const int sbA = slotf(zA);
#pragma unroll
            for (int jj = 0; jj < 8; jj++) {
                const int a = sbA ^ slotf(jj << 6);
                *reinterpret_cast<u64*>(&sre[a]) = cr[jj];
                *reinterpret_cast<u64*>(&sim[a]) = ci[jj];
            }
        }
        __syncwarp();   // A->B exchange is warp-local (same warp bits)

        // ================= tile B =================
        {
            const int sbB = slotf(zB);
#pragma unroll
            for (int jj = 0; jj < 8; jj++) {
                const int a = sbB ^ (jj << 1);
                cr[jj] = *reinterpret_cast<const u64*>(&sre[a]);
                ci[jj] = *reinterpret_cast<const u64*>(&sim[a]);
            }
            gates3<12, 11, 10>(cr, ci, g);   // bits 1,2,3
#pragma unroll
            for (int jj = 0; jj < 8; jj++) {
                const int a = sbB ^ (jj << 1);
                *reinterpret_cast<u64*>(&sre[a]) = cr[jj];
                *reinterpret_cast<u64*>(&sim[a]) = ci[jj];
            }
        }
        __syncthreads();

        // ================= tile C =================
        {
            const int sbC = slotf(zC);
#pragma unroll
            for (int jj = 0; jj < 8; jj++) {
                const int a = sbC ^ slotf(jj << 9);
                cr[jj] = *reinterpret_cast<const u64*>(&sre[a]);
                ci[jj] = *reinterpret_cast<const u64*>(&sim[a]);
            }
            gates3<4, 3, 2>(cr, ci, g);      // bits 9,10,11
            shflg(cr, ci, g[1], 8,  l3);     // q1 (bit12)
            shflg(cr, ci, g[0], 16, l4);     // q0 (bit13)
            if (t < 2) {
#pragma unroll
                for (int jj = 0; jj < 8; jj++) {
                    const int a = sbC ^ slotf(jj << 9);
                    *reinterpret_cast<u64*>(&sre[a]) = cr[jj];
                    *reinterpret_cast<u64*>(&sim[a]) = ci[jj];
                }
            }
        }
        if (t < 2) __syncthreads();
    }

    // ---- measurement from tile-C registers; final entangle perm arithmetic -
    // y = sxf(z). jj bits at z9,z10,z11; z0 = packed lane; rest per-thread.
    u64 tE = 0, tO = 0, o11 = 0, o10 = 0;
#pragma unroll
    for (int jj = 0; jj < 8; jj++) {
        const u64 p2 = fma2(ci[jj], ci[jj], mul2(cr[jj], cr[jj]));
        if (__popc(jj) & 1) tO = add2(tO, p2);
        else                tE = add2(tE, p2);
        if ((jj >> 2) & 1)               o11 = add2(o11, p2);
        if (((jj >> 1) ^ (jj >> 2)) & 1) o10 = add2(o10, p2);
    }

    float s[NQ], tsum;
    {
        float tEl, tEh, tOl, tOh, a2, b2;
        unpk(tE, tEl, tEh);
        unpk(tO, tOl, tOh);
        const float tE2 = tEl + tEh, tO2 = tOl + tOh;
        tsum = tE2 + tO2;
        float o11s, o10s;
        unpk(o11, a2, b2); o11s = a2 + b2;
        unpk(o10, a2, b2); o10s = a2 + b2;

        // constant z bits (everything except jj and z0)
        const int zc = zC;
        // qubit q <-> y bit p = 13-q
        s[0] = ((zc >> 13) & 1) ? tsum : 0.f;                       // p=13
        s[1] = (__popc(zc >> 12) & 1) ? tsum : 0.f;                 // p=12
        s[2] = (__popc(zc >> 11) & 1) ? (tsum - o11s) : o11s;       // p=11
        s[3] = (__popc(zc >> 10) & 1) ? (tsum - o10s) : o10s;       // p=10
        s[4] = (__popc(zc >> 9) & 1) ? tE2 : tO2;                   // p=9
#pragma unroll
        for (int q = 5; q < 13; q++) {                              // p=8..1
            const int p = 13 - q;
            s[q] = (__popc(zc >> p) & 1) ? tE2 : tO2;
        }
        const int c0 = __popc(zc) & 1;                              // p=0
        s[13] = c0 ? (tEl + tOh) : (tOl + tEh);
    }

#pragma unroll
    for (int o = 16; o; o >>= 1) {
        tsum += __shfl_xor_sync(0xFFFFFFFFu, tsum, o);
#pragma unroll
        for (int q = 0; q < NQ; q++)
            s[q] += __shfl_xor_sync(0xFFFFFFFFu, s[q], o);
    }
    if (lane == 0) {
        red[warp][0] = tsum;
#pragma unroll
        for (int q = 0; q < NQ; q++) red[warp][1 + q] = s[q];
    }
    __syncthreads();

    if (tid < NQ) {
        float tt = 0.f, ss = 0.f;
#pragma unroll
        for (int w = 0; w < 32; w++) {
            tt += red[w][0];
            ss += red[w][1 + tid];
        }
        out[b * NQ + tid] = tt - 2.f * ss;
    }
}

// ---------------------------------------------------------------------------
extern "C" void kernel_launch(void* const* d_in, const int* in_sizes, int n_in,
                              void* d_out, int out_size) {
    const float* x    = (const float*)d_in[0];
    const float* prx  = (const float*)d_in[1];
    const float* pry  = (const float*)d_in[2];
    const float* prz  = (const float*)d_in[3];
    const float* pent = (const float*)d_in[4];
    float* out = (float*)d_out;

    const int B = in_sizes[0] / NQ;
    const size_t smem = 2 * NSTATE * sizeof(float);  // 131072 bytes SoA

    cudaFuncSetAttribute(qc_kernel,
                         cudaFuncAttributeMaxDynamicSharedMemorySize,
                         (int)smem);
    qc_kernel<<<B, NT, smem>>>(x, prx, pry, prz, pent, out);
}